// round 16
// baseline (speedup 1.0000x reference)
#include <cuda_runtime.h>
#include <math.h>

#define B 32
#define L 200
#define DIM 36
#define ET 128
#define NH 64

#define OFF_OUT_TE 0
#define OFF_OUT1   (B*ET*DIM)
#define OFF_LOGITS (2*B*ET*DIM)
#define OFF_SXG    (OFF_LOGITS + B*2)
#define OFF_SOUT   (OFF_SXG + B*DIM*DIM)
#define OFF_QP     (OFF_SOUT + B*DIM*DIM)

typedef unsigned long long ull;

__device__ ull   g_qk2[ET*ET];
__device__ float g_qkb[ET];
__device__ float g_embT[B*ET*256];
__device__ float g_Y[B*L*108];
__device__ float g_GI[B*ET*192];
__device__ float g_hfin[B*NH];
__device__ int   g_ctr;
__device__ int   g_bctr[B];

__device__ __forceinline__ ull pk2(float lo, float hi) {
    ull r; asm("mov.b64 %0, {%1,%2};" : "=l"(r) : "f"(lo), "f"(hi)); return r;
}
__device__ __forceinline__ void ffma2(ull& d, ull a, ull b) {
    asm("fma.rn.f32x2 %0, %1, %2, %0;" : "+l"(d) : "l"(a), "l"(b));
}
__device__ __forceinline__ void cpa16(unsigned s, const void* g) {
    asm volatile("cp.async.cg.shared.global [%0], [%1], 16;" :: "r"(s), "l"(g));
}
#define CPCOMMIT() asm volatile("cp.async.commit_group;")
#define CPWAIT0()  asm volatile("cp.async.wait_group 0;")

#define N3 (B*L*108)

// ---- k_front: 224 blocks ----
__global__ void __launch_bounds__(256) k_front(
        const float* __restrict__ ts, const float* __restrict__ pw,
        const float* __restrict__ pb, const float* __restrict__ tw,
        const float* __restrict__ tb, const float* __restrict__ x,
        const float* __restrict__ qp, const float* __restrict__ qw,
        const float* __restrict__ qb, const float* __restrict__ kw,
        const float* __restrict__ kb, float* __restrict__ out) {
    __shared__ float shb[7200];
    int blk = blockIdx.x, tid = threadIdx.x;
    if (blk < 64) {
        int b = blk >> 1, half = blk & 1;
        float* spw = shb;
        float* spb = shb + 64;
        if (tid < 64) {
            int jg = half*64 + tid;
            spw[tid] = (jg >= 1) ? pw[jg-1] : 0.f;
            spb[tid] = (jg >= 1) ? pb[jg-1] : 0.f;
        }
        int l = tid;
        float t = (l < L) ? ts[b*L + l] : 0.f;
        float tl0 = fmaf(t, tw[0], tb[0]);
        __syncthreads();
        float* dst = g_embT + (b*ET + half*64)*256 + l;
        #pragma unroll 4
        for (int j0 = 0; j0 < 64; j0++) {
            int jg = half*64 + j0;
            float v;
            if (l >= L) v = 0.f;
            else if (jg == 0) v = tl0;
            else v = __sinf(fmaf(t, spw[j0], spb[j0]));
            dst[j0*256] = v;
        }
        return;
    }
    if (blk < 128) {
        for (int k = (blk - 64)*256 + tid; k < N3; k += 64*256) {
            int b = k / 21600, rem = k % 21600;
            int l = rem / 108, c = rem % 108;
            const float* xr = x + (b*L + l)*72;
            g_Y[k] = (c < 72) ? xr[c] * xr[36 + (c % 36)] : xr[c - 36];
        }
        return;
    }
    if (blk < 192) {
        if (blk == 128) {
            if (tid == 0) g_ctr = 0;
            if (tid < 32) g_bctr[tid] = 0;
        }
        int rr = tid >> 7, j = tid & 127;
        int r = (blk - 128)*2 + rr;
        float* e2  = shb;
        float* qr2 = shb + 256;
        float t = qp[r];
        e2[rr*128 + j] = (j == 0) ? fmaf(t, tw[0], tb[0]) : __sinf(fmaf(t, pw[j-1], pb[j-1]));
        if (j == 0) out[OFF_QP + r] = t;
        __syncthreads();
        float a = qb[j];
        #pragma unroll 8
        for (int d = 0; d < ET; d++) a = fmaf(qw[j*ET + d], e2[rr*128 + d], a);
        qr2[rr*128 + j] = a;
        __syncthreads();
        const float inv = 0.08838834764831845f;
        float a2 = 0.f;
        #pragma unroll 8
        for (int d = 0; d < ET; d++) a2 = fmaf(qr2[rr*128 + d], kw[d*ET + j], a2);
        float v = a2 * inv;
        g_qk2[r*ET + j] = pk2(v, v);
        if (j == 0) {
            float s = 0.f;
            for (int d = 0; d < ET; d++) s = fmaf(qr2[rr*128 + d], kb[d], s);
            g_qkb[r] = s * inv;
        }
        return;
    }
    {   // gram-sxg
        int b = blk - 192;
        float* sxs = shb;
        for (int i = tid; i < L*36; i += 256) sxs[i] = x[(b*L + i/36)*72 + i%36];
        __syncthreads();
        if (tid < 144) {
            int d0 = (tid / 12) * 3, e0 = (tid % 12) * 3;
            float a[3][3];
            #pragma unroll
            for (int i = 0; i < 3; i++)
                #pragma unroll
                for (int j = 0; j < 3; j++) a[i][j] = 0.f;
            for (int r = 0; r < L; r++) {
                float u0 = sxs[r*36+d0], u1 = sxs[r*36+d0+1], u2 = sxs[r*36+d0+2];
                float v0 = sxs[r*36+e0], v1 = sxs[r*36+e0+1], v2 = sxs[r*36+e0+2];
                a[0][0]=fmaf(u0,v0,a[0][0]); a[0][1]=fmaf(u0,v1,a[0][1]); a[0][2]=fmaf(u0,v2,a[0][2]);
                a[1][0]=fmaf(u1,v0,a[1][0]); a[1][1]=fmaf(u1,v1,a[1][1]); a[1][2]=fmaf(u1,v2,a[1][2]);
                a[2][0]=fmaf(u2,v0,a[2][0]); a[2][1]=fmaf(u2,v1,a[2][1]); a[2][2]=fmaf(u2,v2,a[2][2]);
            }
            #pragma unroll
            for (int i = 0; i < 3; i++)
                #pragma unroll
                for (int j = 0; j < 3; j++)
                    out[OFF_SXG + b*1296 + (d0+i)*36 + (e0+j)] = rintf(1.f/(1.f + expf(-a[i][j])));
        }
    }
}

// ---- k_att: scores+softmax+attention+ow+GI; 8th block/batch: gru+sout; 32nd batch: classifier ----
__global__ void __launch_bounds__(256, 2) k_att(const int* __restrict__ rm,
        const float* __restrict__ ow, const float* __restrict__ ob,
        const float* __restrict__ wih, const float* __restrict__ bih,
        const float* __restrict__ whh, const float* __restrict__ bhh_p,
        const float* __restrict__ si, const float* __restrict__ stw,
        const float* __restrict__ stb, const float* __restrict__ c1w,
        const float* __restrict__ c1b, const float* __restrict__ bng,
        const float* __restrict__ bnb, const float* __restrict__ c2w,
        const float* __restrict__ c2b, float* __restrict__ out) {
    extern __shared__ __align__(16) float sm[];
    __shared__ int lastf, lastc;
    ull*  qs = (ull*)sm;
    ull*  et = (ull*)(sm + 4096);
    ulonglong2* Epk = (ulonglong2*)sm;
    float* ys = sm + 14336;
    float* rmf = sm + 22528;
    int q0 = blockIdx.x * 16, b = blockIdx.y, tid = threadIdx.x;
    int w = tid >> 5, tc = tid & 31;
    unsigned qs_s = (unsigned)__cvta_generic_to_shared(qs);
    unsigned et_s = (unsigned)__cvta_generic_to_shared(et);
    unsigned ys_s = (unsigned)__cvta_generic_to_shared(ys);
    unsigned sm_s = (unsigned)__cvta_generic_to_shared(sm);

    if (tid < 224) rmf[tid] = (tid < 200) ? (float)rm[b*L + tid] : 0.f;

    {   // initial stage
        int row = tid >> 3;
        for (int ck = tid & 7; ck < 27; ck += 8)
            cpa16(ys_s + row*512 + ck*16, (const char*)(g_Y + (b*L + row)*108) + ck*16);
        for (int i = tid; i < 1024; i += 256)
            cpa16(qs_s + i*16, (const char*)(g_qk2 + q0*ET) + i*16);
        for (int i = tid; i < 1024; i += 256)
            cpa16(et_s + i*16, (const char*)g_embT + (size_t)(b*ET)*1024 + i*16);
        CPCOMMIT();
    }

    ull acc[2][4];
    #pragma unroll
    for (int a = 0; a < 2; a++)
        #pragma unroll
        for (int c = 0; c < 4; c++) acc[a][c] = 0;
    for (int ch = 0; ch < 8; ch++) {
        CPWAIT0();
        __syncthreads();
        if (ch < 7) {
            unsigned dst = et_s + (((ch+1) & 1) ? 16384u : 0u);
            const char* es = (const char*)g_embT + (size_t)(b*ET + (ch+1)*16)*1024;
            for (int i = tid; i < 1024; i += 256) cpa16(dst + i*16, es + i*16);
            CPCOMMIT();
        }
        const ull* etb = et + (ch & 1)*2048;
        #pragma unroll
        for (int jj = 0; jj < 16; jj++) {
            int jg = ch*16 + jj;
            ull qv0 = qs[(2*w)*128 + jg];
            ull qv1 = qs[(2*w + 1)*128 + jg];
            ull ev[4];
            #pragma unroll
            for (int li = 0; li < 4; li++) ev[li] = etb[jj*128 + tc + 32*li];
            #pragma unroll
            for (int li = 0; li < 4; li++) { ffma2(acc[0][li], qv0, ev[li]); ffma2(acc[1][li], qv1, ev[li]); }
        }
    }
    __syncthreads();

    #pragma unroll
    for (int qi = 0; qi < 2; qi++) {
        int q = q0 + 2*w + qi;
        float qkbv = g_qkb[q];
        float slo[4], shi[4], m = -1e30f;
        #pragma unroll
        for (int li = 0; li < 4; li++) {
            float2 f = *(float2*)&acc[qi][li];
            slo[li] = f.x + qkbv; shi[li] = f.y + qkbv;
            if (li < 3 || tc < 4) m = fmaxf(m, fmaxf(slo[li], shi[li]));
        }
        #pragma unroll
        for (int off = 16; off; off >>= 1) m = fmaxf(m, __shfl_xor_sync(0xffffffffu, m, off));
        #pragma unroll
        for (int li = 0; li < 4; li++) {
            int p = tc + 32*li;
            if (p < 100) {
                float Elo = __expf(slo[li] - m), Ehi = __expf(shi[li] - m);
                float flo = Elo * rmf[2*p], fhi = Ehi * rmf[2*p + 1];
                ulonglong2 v0; v0.x = pk2(Elo, Elo); v0.y = pk2(flo, flo);
                ulonglong2 v1; v1.x = pk2(Ehi, Ehi); v1.y = pk2(fhi, fhi);
                Epk[(2*w + qi)*224 + 2*p]     = v0;
                Epk[(2*w + qi)*224 + 2*p + 1] = v1;
            } else if (p < 112) {
                ulonglong2 z; z.x = 0; z.y = 0;
                Epk[(2*w + qi)*224 + 2*p]     = z;
                Epk[(2*w + qi)*224 + 2*p + 1] = z;
            }
        }
    }

    ull a00=0,a01=0,a10=0,a11=0, b00=0,b01=0,b10=0,b11=0;
    for (int t = 0; t < 7; t++) {
        CPWAIT0();
        __syncthreads();
        if (t < 6) {
            int l0 = (t+1)*32;
            unsigned dst = ys_s + ((t+1) & 1)*16384u;
            int row = tid >> 3, gl = l0 + row;
            if (gl < L)
                for (int ck = tid & 7; ck < 27; ck += 8)
                    cpa16(dst + row*512 + ck*16, (const char*)(g_Y + (b*L + gl)*108) + ck*16);
            CPCOMMIT();
        }
        const float* yb_ = ys + (t & 1)*4096;
        const ulonglong2* e0p = Epk + (2*w)*224 + t*32;
        const ulonglong2* e1p = Epk + (2*w + 1)*224 + t*32;
        #pragma unroll 8
        for (int l = 0; l < 32; l++) {
            ulonglong2 E0 = e0p[l];
            ulonglong2 E1 = e1p[l];
            ull ya = *(const ull*)&yb_[l*128 + 2*tc];
            ull yc = *(const ull*)&yb_[l*128 + 2*tc + 64];
            ffma2(a00, E0.x, ya); ffma2(a01, E0.x, yc);
            ffma2(b00, E0.y, ya); ffma2(b01, E0.y, yc);
            ffma2(a10, E1.x, ya); ffma2(a11, E1.x, yc);
            ffma2(b10, E1.y, ya); ffma2(b11, E1.y, yc);
        }
    }
    __syncthreads();
    float* Cs = sm;
    float* os = sm + 4096;
    float* ot = sm + 6400;
    float* wih_s = sm + 6976;
    float* ow_s  = sm + 13888;
    *(ull*)&Cs[(2*w)*256 + 2*tc]         = a00;
    *(ull*)&Cs[(2*w)*256 + 2*tc + 64]    = a01;
    *(ull*)&Cs[(2*w)*256 + 2*tc + 128]   = b00;
    *(ull*)&Cs[(2*w)*256 + 2*tc + 192]   = b01;
    *(ull*)&Cs[(2*w+1)*256 + 2*tc]       = a10;
    *(ull*)&Cs[(2*w+1)*256 + 2*tc + 64]  = a11;
    *(ull*)&Cs[(2*w+1)*256 + 2*tc + 128] = b10;
    *(ull*)&Cs[(2*w+1)*256 + 2*tc + 192] = b11;
    for (int i = tid; i < 1728; i += 256)
        cpa16(sm_s + 6976*4 + i*16, (const char*)wih + i*16);
    for (int i = tid; i < 648; i += 256)
        cpa16(sm_s + 13888*4 + i*16, (const char*)ow + i*16);
    CPCOMMIT();
    __syncthreads();
    for (int i = tid; i < 16*144; i += 256) {
        int q = i / 144, c = i % 144, m = (c >= 72), d = c - m*72;
        os[i] = __fdividef(Cs[q*256 + m*128 + d], Cs[q*256 + m*128 + 72 + (d >= 36 ? d - 36 : d)]);
    }
    CPWAIT0();
    __syncthreads();
    for (int i = tid; i < 16*72; i += 256) {
        int q = i / 72, c = i - q*72, m = (c >= 36), dd = c - m*36;
        const ull* osr = (const ull*)(os + q*144 + m*72);
        const ull* owr = (const ull*)(ow_s + dd*72);
        ull ac = 0;
        #pragma unroll
        for (int d = 0; d < 36; d++) ffma2(ac, osr[d], owr[d]);
        float2 f = *(float2*)&ac;
        float a = ob[dd] + f.x + f.y;
        out[(m ? OFF_OUT1 : OFF_OUT_TE) + (b*ET + q0 + q)*DIM + dd] = a;
        if (m == 0) ot[q*36 + dd] = a;
    }
    __syncthreads();
    {
        int grp = tid >> 6, j0 = tid & 63;
        for (int q = grp; q < 16; q += 4)
            for (int j = j0; j < 192; j += 64) {
                const ull* otr = (const ull*)(ot + q*36);
                const ull* wr  = (const ull*)(wih_s + j*36);
                ull ac = 0;
                #pragma unroll
                for (int d = 0; d < 18; d++) ffma2(ac, otr[d], wr[d]);
                float2 f = *(float2*)&ac;
                g_GI[(b*ET + q0 + q)*192 + j] = bih[j] + f.x + f.y;
            }
    }
    // ---- per-batch completion: 8th block runs gru + sout ----
    __syncthreads();
    __threadfence();
    if (tid == 0) lastf = (atomicAdd(&g_bctr[b], 1) == 7);
    __syncthreads();
    if (!lastf) return;
    __threadfence();
    // ---- GRU for batch b (tid<192 compute, all 256 barrier) ----
    {
        float* h   = sm;
        float* s   = sm + 128;
        float* gin = sm + 320;
        ull wp[32];
        float bhh = 0.f, gcur = 0.f;
        const float* gi = g_GI + b*ET*192;
        if (tid < 192) {
            const ull* whh2 = (const ull*)whh;
            #pragma unroll
            for (int i = 0; i < 32; i++) wp[i] = whh2[tid*32 + i];
            bhh = bhh_p[tid];
            gcur = gi[tid];
        }
        if (tid < 64) { h[tid] = 0.f; h[64 + tid] = 0.f; }
        __syncthreads();
        int p = 0;
        for (int t = 0; t < ET; t++) {
            float gnext = (tid < 192 && t < ET-1) ? gi[(t+1)*192 + tid] : 0.f;
            if (tid < 192) {
                ull a[8];
                #pragma unroll
                for (int i = 0; i < 8; i++) a[i] = 0;
                const ulonglong2* h2 = (const ulonglong2*)(h + p*64);
                #pragma unroll
                for (int i = 0; i < 16; i++) {
                    ulonglong2 hv = h2[i];
                    ffma2(a[(2*i) & 7],     wp[2*i],     hv.x);
                    ffma2(a[(2*i + 1) & 7], wp[2*i + 1], hv.y);
                }
                float gh = bhh;
                #pragma unroll
                for (int i = 0; i < 8; i++) {
                    float2 f = *(float2*)&a[i];
                    gh += f.x + f.y;
                }
                if (tid < 128) s[tid] = gcur + gh;
                else { s[tid] = gh; gin[tid - 128] = gcur; }
            }
            __syncthreads();
            if (tid < 64) {
                float r = __fdividef(1.f, 1.f + __expf(-s[tid]));
                float z = __fdividef(1.f, 1.f + __expf(-s[64 + tid]));
                float narg = fmaf(r, s[128 + tid], gin[tid]);
                float e2 = __expf(2.f * narg);
                float n = 1.f - __fdividef(2.f, e2 + 1.f);
                h[(p ^ 1)*64 + tid] = fmaf(z, h[p*64 + tid] - n, n);
            }
            __syncthreads();
            gcur = gnext;
            p ^= 1;
        }
        if (tid < 64) g_hfin[b*64 + tid] = h[p*64 + tid];
    }
    // ---- sout for batch b ----
    __syncthreads();
    {
        float* ot2 = sm;
        for (int i = tid; i < ET*36; i += 256) ot2[i] = out[OFF_OUT_TE + b*ET*36 + i];
        __syncthreads();
        if (tid < 144) {
            int d0 = (tid / 12) * 3, e0 = (tid % 12) * 3;
            float a[3][3];
            #pragma unroll
            for (int i = 0; i < 3; i++)
                #pragma unroll
                for (int j = 0; j < 3; j++) a[i][j] = 0.f;
            for (int r = 0; r < ET; r++) {
                float u0 = ot2[r*36+d0], u1 = ot2[r*36+d0+1], u2 = ot2[r*36+d0+2];
                float v0 = ot2[r*36+e0], v1 = ot2[r*36+e0+1], v2 = ot2[r*36+e0+2];
                a[0][0]=fmaf(u0,v0,a[0][0]); a[0][1]=fmaf(u0,v1,a[0][1]); a[0][2]=fmaf(u0,v2,a[0][2]);
                a[1][0]=fmaf(u1,v0,a[1][0]); a[1][1]=fmaf(u1,v1,a[1][1]); a[1][2]=fmaf(u1,v2,a[1][2]);
                a[2][0]=fmaf(u2,v0,a[2][0]); a[2][1]=fmaf(u2,v1,a[2][1]); a[2][2]=fmaf(u2,v2,a[2][2]);
            }
            #pragma unroll
            for (int i = 0; i < 3; i++)
                #pragma unroll
                for (int j = 0; j < 3; j++)
                    out[OFF_SOUT + b*1296 + (d0+i)*36 + (e0+j)] = 1.f/(1.f + expf(-a[i][j]));
        }
    }
    // ---- global completion: 32nd batch-finisher runs classifier ----
    __threadfence();
    __syncthreads();
    if (tid == 0) lastc = (atomicAdd(&g_ctr, 1) == 31);
    __syncthreads();
    if (!lastc) return;
    __threadfence();
    {
        float* ci = sm;                   // [2304]
        float* zs = sm + 2304;            // [2304]
        ull*   c1t2 = (ull*)(sm + 4608);  // [36*73]
        float* mus = sm + 9864;
        float* ivs = sm + 9936;
        for (int i = tid; i < 72*36; i += 256) {
            int j = i / 36, dp = i - j*36;
            c1t2[dp*73 + j] = *(const ull*)(c1w + j*72 + 2*dp);
        }
        for (int i = tid; i < 32*8; i += 256) {
            int bb = i >> 3, jj = i & 7;
            float a = stb[jj];
            #pragma unroll
            for (int ss = 0; ss < 9; ss++) a = fmaf(si[bb*9 + ss], stw[jj*9 + ss], a);
            ci[bb*72 + 64 + jj] = a;
        }
        for (int i = tid; i < 32*64; i += 256) {
            int bb = i >> 6, j = i & 63;
            ci[bb*72 + j] = g_hfin[i];
        }
        __syncthreads();
        for (int i = tid; i < 2304; i += 256) {
            int bb = i / 72, j = i - bb*72;
            const ull* cib = (const ull*)(ci + bb*72);
            ull a0 = 0, a1 = 0;
            #pragma unroll
            for (int dp = 0; dp < 36; dp += 2) {
                ffma2(a0, cib[dp],     c1t2[dp*73 + j]);
                ffma2(a1, cib[dp + 1], c1t2[(dp + 1)*73 + j]);
            }
            float2 f0 = *(float2*)&a0, f1 = *(float2*)&a1;
            zs[i] = c1b[j] + (f0.x + f0.y) + (f1.x + f1.y);
        }
        __syncthreads();
        if (tid < 72) {
            float mu = 0.f;
            #pragma unroll 8
            for (int bb = 0; bb < 32; bb++) mu += zs[bb*72 + tid];
            mu *= (1.f / 32.f);
            float m2 = 0.f;
            #pragma unroll 8
            for (int bb = 0; bb < 32; bb++) { float d = zs[bb*72 + tid] - mu; m2 = fmaf(d, d, m2); }
            mus[tid] = mu;
            ivs[tid] = rsqrtf(m2 * (1.f / 32.f) + 1e-5f);
        }
        __syncthreads();
        for (int i = tid; i < 2304; i += 256) {
            int j = i % 72;
            float zn = (zs[i] - mus[j]) * ivs[j] * bng[j] + bnb[j];
            zs[i] = zn * 0.5f * (1.f + erff(zn * 0.7071067811865475f));
        }
        __syncthreads();
        if (tid < 64) {
            int bb = tid >> 1, c = tid & 1;
            float a = c2b[c];
            #pragma unroll
            for (int d = 0; d < 72; d++) a = fmaf(zs[bb*72 + d], c2w[c*72 + d], a);
            out[OFF_LOGITS + bb*2 + c] = a;
        }
    }
}

extern "C" void kernel_launch(void* const* d_in, const int* in_sizes, int n_in,
                              void* d_out, int out_size) {
    const float* x    = (const float*)d_in[0];
    const float* ts   = (const float*)d_in[1];
    const float* si   = (const float*)d_in[2];
    const float* qp   = (const float*)d_in[3];
    const float* pw   = (const float*)d_in[4];
    const float* pb   = (const float*)d_in[5];
    const float* tw   = (const float*)d_in[6];
    const float* tb   = (const float*)d_in[7];
    const float* qw   = (const float*)d_in[8];
    const float* qb   = (const float*)d_in[9];
    const float* kw   = (const float*)d_in[10];
    const float* kb   = (const float*)d_in[11];
    const float* ow   = (const float*)d_in[12];
    const float* ob   = (const float*)d_in[13];
    const float* wih  = (const float*)d_in[14];
    const float* whh  = (const float*)d_in[15];
    const float* bih  = (const float*)d_in[16];
    const float* bhh  = (const float*)d_in[17];
    const float* stw  = (const float*)d_in[18];
    const float* stb  = (const float*)d_in[19];
    const float* c1w  = (const float*)d_in[20];
    const float* c1b  = (const float*)d_in[21];
    const float* bng  = (const float*)d_in[22];
    const float* bnb  = (const float*)d_in[23];
    const float* c2w  = (const float*)d_in[24];
    const float* c2b  = (const float*)d_in[25];
    const int*   rm   = (const int*)d_in[26];
    float* out = (float*)d_out;

    cudaFuncSetAttribute(k_att, cudaFuncAttributeMaxDynamicSharedMemorySize, 91008);

    k_front<<<224, 256>>>(ts, pw, pb, tw, tb, x, qp, qw, qb, kw, kb, out);
    k_att<<<dim3(8, B), 256, 91008>>>(rm, ow, ob, wih, bih, whh, bhh, si, stw, stb,
                                      c1w, c1b, bng, bnb, c2w, c2b, out);
}

// round 17
// speedup vs baseline: 1.0984x; 1.0984x over previous
#include <cuda_runtime.h>
#include <math.h>

#define B 32
#define L 200
#define DIM 36
#define ET 128
#define NH 64

#define OFF_OUT_TE 0
#define OFF_OUT1   (B*ET*DIM)
#define OFF_LOGITS (2*B*ET*DIM)
#define OFF_SXG    (OFF_LOGITS + B*2)
#define OFF_SOUT   (OFF_SXG + B*DIM*DIM)
#define OFF_QP     (OFF_SOUT + B*DIM*DIM)

typedef unsigned long long ull;

__device__ ull   g_qk2[ET*ET];     // pair-interleaved: [r>>1][j][2]
__device__ float g_qkb[ET];
__device__ float g_embT[B*ET*256];
__device__ float g_Y[B*L*108];
__device__ float g_GI[B*ET*192];
__device__ float g_hfin[B*NH];
__device__ int   g_ctr;

__device__ __forceinline__ ull pk2(float lo, float hi) {
    ull r; asm("mov.b64 %0, {%1,%2};" : "=l"(r) : "f"(lo), "f"(hi)); return r;
}
__device__ __forceinline__ void ffma2(ull& d, ull a, ull b) {
    asm("fma.rn.f32x2 %0, %1, %2, %0;" : "+l"(d) : "l"(a), "l"(b));
}
__device__ __forceinline__ void cpa16(unsigned s, const void* g) {
    asm volatile("cp.async.cg.shared.global [%0], [%1], 16;" :: "r"(s), "l"(g));
}
#define CPCOMMIT() asm volatile("cp.async.commit_group;")
#define CPWAIT0()  asm volatile("cp.async.wait_group 0;")

#define N3 (B*L*108)

// ---- k_front: 192 fat blocks, one wave ----
__global__ void __launch_bounds__(256) k_front(
        const float* __restrict__ ts, const float* __restrict__ pw,
        const float* __restrict__ pb, const float* __restrict__ tw,
        const float* __restrict__ tb, const float* __restrict__ x,
        const float* __restrict__ qp, const float* __restrict__ qw,
        const float* __restrict__ qb, const float* __restrict__ kw,
        const float* __restrict__ kb, float* __restrict__ out) {
    int blk = blockIdx.x, tid = threadIdx.x;
    if (blk < 64) {
        int b = blk >> 1, half = blk & 1;
        __shared__ float spw[64], spb[64];
        if (tid < 64) {
            int jg = half*64 + tid;
            spw[tid] = (jg >= 1) ? pw[jg-1] : 0.f;
            spb[tid] = (jg >= 1) ? pb[jg-1] : 0.f;
        }
        int l = tid;
        float t = (l < L) ? ts[b*L + l] : 0.f;
        float tl0 = fmaf(t, tw[0], tb[0]);
        __syncthreads();
        float* dst = g_embT + (b*ET + half*64)*256 + l;
        #pragma unroll 4
        for (int j0 = 0; j0 < 64; j0++) {
            int jg = half*64 + j0;
            float v;
            if (l >= L) v = 0.f;
            else if (jg == 0) v = tl0;
            else v = __sinf(fmaf(t, spw[j0], spb[j0]));
            dst[j0*256] = v;
        }
        return;
    }
    if (blk < 128) {
        for (int k = (blk - 64)*256 + tid; k < N3; k += 64*256) {
            int b = k / 21600, rem = k % 21600;
            int l = rem / 108, c = rem % 108;
            const float* xr = x + (b*L + l)*72;
            g_Y[k] = (c < 72) ? xr[c] * xr[36 + (c % 36)] : xr[c - 36];
        }
        return;
    }
    if (blk == 128 && tid == 0) g_ctr = 0;
    // qk: 64 blocks, 2 r each; pair-interleaved output
    int rr = tid >> 7, j = tid & 127;
    int r = (blk - 128)*2 + rr;
    __shared__ float e2[2][128], qr2[2][128];
    float t = qp[r];
    e2[rr][j] = (j == 0) ? fmaf(t, tw[0], tb[0]) : __sinf(fmaf(t, pw[j-1], pb[j-1]));
    if (j == 0) out[OFF_QP + r] = t;
    __syncthreads();
    float a = qb[j];
    #pragma unroll 8
    for (int d = 0; d < ET; d++) a = fmaf(qw[j*ET + d], e2[rr][d], a);
    qr2[rr][j] = a;
    __syncthreads();
    const float inv = 0.08838834764831845f;
    float a2 = 0.f;
    #pragma unroll 8
    for (int d = 0; d < ET; d++) a2 = fmaf(qr2[rr][d], kw[d*ET + j], a2);
    float v = a2 * inv;
    g_qk2[((r >> 1)*128 + j)*2 + (r & 1)] = pk2(v, v);
    if (j == 0) {
        float s = 0.f;
        for (int d = 0; d < ET; d++) s = fmaf(qr2[rr][d], kb[d], s);
        g_qkb[r] = s * inv;
    }
}

// ---- k_att: fused scores+softmax+attention + ow + GI; grid (8,B), 256 thr, 91008B smem ----
__global__ void __launch_bounds__(256, 2) k_att(const int* __restrict__ rm,
                                             const float* __restrict__ ow, const float* __restrict__ ob,
                                             const float* __restrict__ wih, const float* __restrict__ bih,
                                             float* __restrict__ out) {
    extern __shared__ __align__(16) float sm[];
    ull*  qs = (ull*)sm;
    ull*  et = (ull*)(sm + 4096);
    ulonglong2* Epk = (ulonglong2*)sm;
    float* ys = sm + 14336;
    float* rmf = sm + 22528;
    int q0 = blockIdx.x * 16, b = blockIdx.y, tid = threadIdx.x;
    int w = tid >> 5, tc = tid & 31;
    unsigned qs_s = (unsigned)__cvta_generic_to_shared(qs);
    unsigned et_s = (unsigned)__cvta_generic_to_shared(et);
    unsigned ys_s = (unsigned)__cvta_generic_to_shared(ys);
    unsigned sm_s = (unsigned)__cvta_generic_to_shared(sm);

    if (tid < 224) rmf[tid] = (tid < 200) ? (float)rm[b*L + tid] : 0.f;

    {   // initial stage: ys tile0 + qs + et chunk0
        int row = tid >> 3;
        for (int ck = tid & 7; ck < 27; ck += 8)
            cpa16(ys_s + row*512 + ck*16, (const char*)(g_Y + (b*L + row)*108) + ck*16);
        for (int i = tid; i < 1024; i += 256)
            cpa16(qs_s + i*16, (const char*)(g_qk2 + q0*ET) + i*16);
        for (int i = tid; i < 1024; i += 256)
            cpa16(et_s + i*16, (const char*)g_embT + (size_t)(b*ET)*1024 + i*16);
        CPCOMMIT();
    }

    ull acc[2][4];
    #pragma unroll
    for (int a = 0; a < 2; a++)
        #pragma unroll
        for (int c = 0; c < 4; c++) acc[a][c] = 0;
    for (int ch = 0; ch < 8; ch++) {
        CPWAIT0();
        __syncthreads();
        if (ch < 7) {
            unsigned dst = et_s + (((ch+1) & 1) ? 16384u : 0u);
            const char* es = (const char*)g_embT + (size_t)(b*ET + (ch+1)*16)*1024;
            for (int i = tid; i < 1024; i += 256) cpa16(dst + i*16, es + i*16);
            CPCOMMIT();
        }
        const ulonglong2* qs2 = (const ulonglong2*)qs;
        const ull* etb = et + (ch & 1)*2048;
        #pragma unroll
        for (int jj = 0; jj < 16; jj++) {
            int jg = ch*16 + jj;
            ulonglong2 qv = qs2[w*128 + jg];   // .x = q 2w, .y = q 2w+1
            ull ev[4];
            #pragma unroll
            for (int li = 0; li < 4; li++) ev[li] = etb[jj*128 + tc + 32*li];
            #pragma unroll
            for (int li = 0; li < 4; li++) { ffma2(acc[0][li], qv.x, ev[li]); ffma2(acc[1][li], qv.y, ev[li]); }
        }
    }
    __syncthreads();

    #pragma unroll
    for (int qi = 0; qi < 2; qi++) {
        int q = q0 + 2*w + qi;
        float qkbv = g_qkb[q];
        float slo[4], shi[4], m = -1e30f;
        #pragma unroll
        for (int li = 0; li < 4; li++) {
            float2 f = *(float2*)&acc[qi][li];
            slo[li] = f.x + qkbv; shi[li] = f.y + qkbv;
            if (li < 3 || tc < 4) m = fmaxf(m, fmaxf(slo[li], shi[li]));
        }
        #pragma unroll
        for (int off = 16; off; off >>= 1) m = fmaxf(m, __shfl_xor_sync(0xffffffffu, m, off));
        #pragma unroll
        for (int li = 0; li < 4; li++) {
            int p = tc + 32*li;
            if (p < 100) {
                float Elo = __expf(slo[li] - m), Ehi = __expf(shi[li] - m);
                float flo = Elo * rmf[2*p], fhi = Ehi * rmf[2*p + 1];
                ulonglong2 v0; v0.x = pk2(Elo, Elo); v0.y = pk2(flo, flo);
                ulonglong2 v1; v1.x = pk2(Ehi, Ehi); v1.y = pk2(fhi, fhi);
                Epk[(2*w + qi)*224 + 2*p]     = v0;
                Epk[(2*w + qi)*224 + 2*p + 1] = v1;
            } else if (p < 112) {
                ulonglong2 z; z.x = 0; z.y = 0;
                Epk[(2*w + qi)*224 + 2*p]     = z;
                Epk[(2*w + qi)*224 + 2*p + 1] = z;
            }
        }
    }

    ull a00=0,a01=0,a10=0,a11=0, b00=0,b01=0,b10=0,b11=0;
    for (int t = 0; t < 7; t++) {
        CPWAIT0();
        __syncthreads();
        if (t < 6) {
            int l0 = (t+1)*32;
            unsigned dst = ys_s + ((t+1) & 1)*16384u;
            int row = tid >> 3, gl = l0 + row;
            if (gl < L)
                for (int ck = tid & 7; ck < 27; ck += 8)
                    cpa16(dst + row*512 + ck*16, (const char*)(g_Y + (b*L + gl)*108) + ck*16);
            CPCOMMIT();
        }
        const float* yb_ = ys + (t & 1)*4096;
        const ulonglong2* e0p = Epk + (2*w)*224 + t*32;
        const ulonglong2* e1p = Epk + (2*w + 1)*224 + t*32;
        #pragma unroll 8
        for (int l = 0; l < 32; l++) {
            ulonglong2 E0 = e0p[l];
            ulonglong2 E1 = e1p[l];
            ull ya = *(const ull*)&yb_[l*128 + 2*tc];
            ull yc = *(const ull*)&yb_[l*128 + 2*tc + 64];
            ffma2(a00, E0.x, ya); ffma2(a01, E0.x, yc);
            ffma2(b00, E0.y, ya); ffma2(b01, E0.y, yc);
            ffma2(a10, E1.x, ya); ffma2(a11, E1.x, yc);
            ffma2(b10, E1.y, ya); ffma2(b11, E1.y, yc);
        }
    }
    __syncthreads();
    float* Cs = sm;
    float* os = sm + 4096;
    float* ot = sm + 6400;
    float* wih_s = sm + 6976;
    float* ow_s  = sm + 13888;
    *(ull*)&Cs[(2*w)*256 + 2*tc]         = a00;
    *(ull*)&Cs[(2*w)*256 + 2*tc + 64]    = a01;
    *(ull*)&Cs[(2*w)*256 + 2*tc + 128]   = b00;
    *(ull*)&Cs[(2*w)*256 + 2*tc + 192]   = b01;
    *(ull*)&Cs[(2*w+1)*256 + 2*tc]       = a10;
    *(ull*)&Cs[(2*w+1)*256 + 2*tc + 64]  = a11;
    *(ull*)&Cs[(2*w+1)*256 + 2*tc + 128] = b10;
    *(ull*)&Cs[(2*w+1)*256 + 2*tc + 192] = b11;
    for (int i = tid; i < 1728; i += 256)
        cpa16(sm_s + 6976*4 + i*16, (const char*)wih + i*16);
    for (int i = tid; i < 648; i += 256)
        cpa16(sm_s + 13888*4 + i*16, (const char*)ow + i*16);
    CPCOMMIT();
    __syncthreads();
    for (int i = tid; i < 16*144; i += 256) {
        int q = i / 144, c = i % 144, m = (c >= 72), d = c - m*72;
        os[i] = __fdividef(Cs[q*256 + m*128 + d], Cs[q*256 + m*128 + 72 + (d >= 36 ? d - 36 : d)]);
    }
    CPWAIT0();
    __syncthreads();
    for (int i = tid; i < 16*72; i += 256) {
        int q = i / 72, c = i - q*72, m = (c >= 36), dd = c - m*36;
        const ull* osr = (const ull*)(os + q*144 + m*72);
        const ull* owr = (const ull*)(ow_s + dd*72);
        ull ac = 0;
        #pragma unroll
        for (int d = 0; d < 36; d++) ffma2(ac, osr[d], owr[d]);
        float2 f = *(float2*)&ac;
        float a = ob[dd] + f.x + f.y;
        out[(m ? OFF_OUT1 : OFF_OUT_TE) + (b*ET + q0 + q)*DIM + dd] = a;
        if (m == 0) ot[q*36 + dd] = a;
    }
    __syncthreads();
    {
        int grp = tid >> 6, j0 = tid & 63;
        for (int q = grp; q < 16; q += 4)
            for (int j = j0; j < 192; j += 64) {
                const ull* otr = (const ull*)(ot + q*36);
                const ull* wr  = (const ull*)(wih_s + j*36);
                ull ac = 0;
                #pragma unroll
                for (int d = 0; d < 18; d++) ffma2(ac, otr[d], wr[d]);
                float2 f = *(float2*)&ac;
                g_GI[(b*ET + q0 + q)*192 + j] = bih[j] + f.x + f.y;
            }
    }
}

// ---- k_mid: [0,64) gram; [64,96) gru (+ctr); block 96 = classifier (pre-staged, spin) ----
__global__ void __launch_bounds__(576, 1) k_mid(const float* __restrict__ x,
                                                const float* __restrict__ whh,
                                                const float* __restrict__ bhh_p,
                                                const float* __restrict__ si,
                                                const float* __restrict__ stw,
                                                const float* __restrict__ stb,
                                                const float* __restrict__ c1w,
                                                const float* __restrict__ c1b,
                                                const float* __restrict__ bng,
                                                const float* __restrict__ bnb,
                                                const float* __restrict__ c2w,
                                                const float* __restrict__ c2b,
                                                float* __restrict__ out) {
    __shared__ __align__(16) float shb[10008];
    int tid = threadIdx.x;
    if (blockIdx.x < 64) {
        int b = blockIdx.x & 31, which = blockIdx.x >> 5;
        float* sm = shb;
        int n = which ? L : ET;
        if (which == 0) {
            for (int i = tid; i < ET*36; i += 576) sm[i] = out[OFF_OUT_TE + b*ET*36 + i];
        } else {
            for (int i = tid; i < L*36; i += 576) sm[i] = x[(b*L + i/36)*72 + i%36];
        }
        __syncthreads();
        int sub = tid / 144, tile = tid - sub*144;
        int d0 = (tile / 12) * 3, e0 = (tile % 12) * 3;
        int qn = n >> 2, i0 = sub*qn, i1 = i0 + qn;
        float a[3][3];
        #pragma unroll
        for (int i = 0; i < 3; i++)
            #pragma unroll
            for (int j = 0; j < 3; j++) a[i][j] = 0.f;
        for (int r = i0; r < i1; r++) {
            float u0 = sm[r*36+d0], u1 = sm[r*36+d0+1], u2 = sm[r*36+d0+2];
            float v0 = sm[r*36+e0], v1 = sm[r*36+e0+1], v2 = sm[r*36+e0+2];
            a[0][0]=fmaf(u0,v0,a[0][0]); a[0][1]=fmaf(u0,v1,a[0][1]); a[0][2]=fmaf(u0,v2,a[0][2]);
            a[1][0]=fmaf(u1,v0,a[1][0]); a[1][1]=fmaf(u1,v1,a[1][1]); a[1][2]=fmaf(u1,v2,a[1][2]);
            a[2][0]=fmaf(u2,v0,a[2][0]); a[2][1]=fmaf(u2,v1,a[2][1]); a[2][2]=fmaf(u2,v2,a[2][2]);
        }
        __syncthreads();
        float* pr = sm;
        if (sub > 0) {
            #pragma unroll
            for (int i = 0; i < 3; i++)
                #pragma unroll
                for (int j = 0; j < 3; j++) pr[(sub-1)*1296 + tile*9 + i*3 + j] = a[i][j];
        }
        __syncthreads();
        if (sub == 0) {
            int off = which ? OFF_SXG : OFF_SOUT;
            #pragma unroll
            for (int i = 0; i < 3; i++)
                #pragma unroll
                for (int j = 0; j < 3; j++) {
                    float v = a[i][j] + pr[tile*9 + i*3 + j] + pr[1296 + tile*9 + i*3 + j]
                            + pr[2592 + tile*9 + i*3 + j];
                    float sg = 1.f / (1.f + expf(-v));
                    out[off + b*1296 + (d0+i)*36 + (e0+j)] = which ? rintf(sg) : sg;
                }
        }
        return;
    }
    if (blockIdx.x < 96) {
        if (tid >= 192) return;
        int b = blockIdx.x - 64, j = tid;
        float* h   = shb;
        float* s   = shb + 128;
        float* gin = shb + 320;
        ull wp[32];
        const ull* whh2 = (const ull*)whh;
        #pragma unroll
        for (int i = 0; i < 32; i++) wp[i] = whh2[j*32 + i];
        float bhh = bhh_p[j];
        if (j < 64) { h[j] = 0.f; h[64 + j] = 0.f; }
        const float* gi = g_GI + b*ET*192;
        float gcur = gi[j];
        __syncthreads();
        int p = 0;
        for (int t = 0; t < ET; t++) {
            float gnext = (t < ET-1) ? gi[(t+1)*192 + j] : 0.f;
            ull a[8];
            #pragma unroll
            for (int i = 0; i < 8; i++) a[i] = 0;
            const ulonglong2* h2 = (const ulonglong2*)(h + p*64);
            #pragma unroll
            for (int i = 0; i < 16; i++) {
                ulonglong2 hv = h2[i];
                ffma2(a[(2*i) & 7],     wp[2*i],     hv.x);
                ffma2(a[(2*i + 1) & 7], wp[2*i + 1], hv.y);
            }
            float gh = bhh;
            #pragma unroll
            for (int i = 0; i < 8; i++) {
                float2 f = *(float2*)&a[i];
                gh += f.x + f.y;
            }
            if (j < 128) s[j] = gcur + gh;
            else { s[j] = gh; gin[j - 128] = gcur; }
            __syncthreads();
            if (j < 64) {
                float r = __fdividef(1.f, 1.f + __expf(-s[j]));
                float z = __fdividef(1.f, 1.f + __expf(-s[64 + j]));
                float narg = fmaf(r, s[128 + j], gin[j]);
                float e2 = __expf(2.f * narg);
                float n = 1.f - __fdividef(2.f, e2 + 1.f);
                h[(p ^ 1)*64 + j] = fmaf(z, h[p*64 + j] - n, n);
            }
            __syncthreads();
            gcur = gnext;
            p ^= 1;
        }
        if (j < 64) g_hfin[b*64 + j] = h[p*64 + j];
        __threadfence();
        __syncthreads();
        if (j == 0) atomicAdd(&g_ctr, 1);
        return;
    }
    // ---- classifier block (pre-stage, spin on g_ctr, then finish) ----
    float* ci = shb;
    float* zs = shb + 2304;
    ull*   c1t2 = (ull*)(shb + 4608);
    float* mus = shb + 9864;
    float* ivs = shb + 9936;
    for (int i = tid; i < 72*36; i += 576) {
        int j = i / 36, dp = i - j*36;
        c1t2[dp*73 + j] = *(const ull*)(c1w + j*72 + 2*dp);
    }
    for (int i = tid; i < 32*8; i += 576) {
        int b = i >> 3, jj = i & 7;
        float a = stb[jj];
        #pragma unroll
        for (int s = 0; s < 9; s++) a = fmaf(si[b*9 + s], stw[jj*9 + s], a);
        ci[b*72 + 64 + jj] = a;
    }
    if (tid == 0) {
        while (atomicAdd(&g_ctr, 0) < 32) __nanosleep(200);
    }
    __syncthreads();
    __threadfence();
    for (int i = tid; i < 32*64; i += 576) {
        int b = i >> 6, j = i & 63;
        ci[b*72 + j] = g_hfin[i];
    }
    __syncthreads();
    for (int i = tid; i < 2304; i += 576) {
        int b = i / 72, j = i - b*72;
        const ull* cib = (const ull*)(ci + b*72);
        ull a0 = 0, a1 = 0;
        #pragma unroll
        for (int dp = 0; dp < 36; dp += 2) {
            ffma2(a0, cib[dp],     c1t2[dp*73 + j]);
            ffma2(a1, cib[dp + 1], c1t2[(dp + 1)*73 + j]);
        }
        float2 f0 = *(float2*)&a0, f1 = *(float2*)&a1;
        zs[i] = c1b[j] + (f0.x + f0.y) + (f1.x + f1.y);
    }
    __syncthreads();
    if (tid < 72) {
        float mu = 0.f;
        #pragma unroll 8
        for (int b = 0; b < 32; b++) mu += zs[b*72 + tid];
        mu *= (1.f / 32.f);
        float m2 = 0.f;
        #pragma unroll 8
        for (int b = 0; b < 32; b++) { float d = zs[b*72 + tid] - mu; m2 = fmaf(d, d, m2); }
        mus[tid] = mu;
        ivs[tid] = rsqrtf(m2 * (1.f / 32.f) + 1e-5f);
    }
    __syncthreads();
    for (int i = tid; i < 2304; i += 576) {
        int j = i % 72;
        float zn = (zs[i] - mus[j]) * ivs[j] * bng[j] + bnb[j];
        zs[i] = zn * 0.5f * (1.f + erff(zn * 0.7071067811865475f));
    }
    __syncthreads();
    if (tid < 64) {
        int b = tid >> 1, c = tid & 1;
        float a = c2b[c];
        #pragma unroll
        for (int d = 0; d < 72; d++) a = fmaf(zs[b*72 + d], c2w[c*72 + d], a);
        out[OFF_LOGITS + b*2 + c] = a;
    }
}

extern "C" void kernel_launch(void* const* d_in, const int* in_sizes, int n_in,
                              void* d_out, int out_size) {
    const float* x    = (const float*)d_in[0];
    const float* ts   = (const float*)d_in[1];
    const float* si   = (const float*)d_in[2];
    const float* qp   = (const float*)d_in[3];
    const float* pw   = (const float*)d_in[4];
    const float* pb   = (const float*)d_in[5];
    const float* tw   = (const float*)d_in[6];
    const float* tb   = (const float*)d_in[7];
    const float* qw   = (const float*)d_in[8];
    const float* qb   = (const float*)d_in[9];
    const float* kw   = (const float*)d_in[10];
    const float* kb   = (const float*)d_in[11];
    const float* ow   = (const float*)d_in[12];
    const float* ob   = (const float*)d_in[13];
    const float* wih  = (const float*)d_in[14];
    const float* whh  = (const float*)d_in[15];
    const float* bih  = (const float*)d_in[16];
    const float* bhh  = (const float*)d_in[17];
    const float* stw  = (const float*)d_in[18];
    const float* stb  = (const float*)d_in[19];
    const float* c1w  = (const float*)d_in[20];
    const float* c1b  = (const float*)d_in[21];
    const float* bng  = (const float*)d_in[22];
    const float* bnb  = (const float*)d_in[23];
    const float* c2w  = (const float*)d_in[24];
    const float* c2b  = (const float*)d_in[25];
    const int*   rm   = (const int*)d_in[26];
    float* out = (float*)d_out;

    cudaFuncSetAttribute(k_att, cudaFuncAttributeMaxDynamicSharedMemorySize, 91008);

    k_front<<<192, 256>>>(ts, pw, pb, tw, tb, x, qp, qw, qb, kw, kb, out);
    k_att<<<dim3(8, B), 256, 91008>>>(rm, ow, ob, wih, bih, out);
    k_mid<<<97, 576>>>(x, whh, bhh, si, stw, stb, c1w, c1b, bng, bnb, c2w, c2b, out);
}